// round 15
// baseline (speedup 1.0000x reference)
#include <cuda_runtime.h>
#include <cuda_pipeline_primitives.h>
#include <math.h>

#define OUT_DIM 4096
#define DPC     16
#define NCOLS   (OUT_DIM * DPC)   // 65536
#define BATCH   512
#define WPB     256               // threads per block
#define TPB     2                 // tiles per block (double-buffered pipeline)
#define SPAN    3856              // staged floats per tile (need 3841)
#define SPAN4   964               // float4 per tile

// Per-column boost factors, batch-invariant: computed once per launch.
__device__ float g_bf[NCOLS];

__global__ void bf_kernel(const float* __restrict__ duty_cycle,
                          const float* __restrict__ boost_strength) {
    int k = blockIdx.x * blockDim.x + threadIdx.x;
    const float td = (float)OUT_DIM / (float)NCOLS;  // 0.0625
    float bs = boost_strength[0];
    g_bf[k] = expf((td - duty_cycle[k]) * bs);
#if __CUDA_ARCH__ >= 900
    cudaTriggerProgrammaticLaunchCompletion();
#endif
}

__global__ void __launch_bounds__(256)
dkw_kernel(const float* __restrict__ x, float* __restrict__ out) {
    __shared__ float sx[2][SPAN];     // double-buffered x window spans
    __shared__ int   s_bj[WPB];

    const int tid = threadIdx.x;
    const int b = blockIdx.x >> 3;    // batch row (8 block-groups per row)
    const int g = blockIdx.x & 7;     // tile-pair within row: tiles 2g, 2g+1

    const size_t rowoff = (size_t)b * NCOLS;
    const float* xrow = x + rowoff;
    // Over-fetch proof: 3840*15 + 3856 = 61456 < 65536.

    // ---- Prologue: async-stage tile 0's x window (before PDL wait) ----
    {
        const float4* src = reinterpret_cast<const float4*>(xrow + 3840 * (2 * g));
        float4* dst = reinterpret_cast<float4*>(sx[0]);
#pragma unroll 4
        for (int f = tid; f < SPAN4; f += WPB)
            __pipeline_memcpy_async(&dst[f], &src[f], 16);
        __pipeline_commit();
    }
#if __CUDA_ARCH__ >= 900
    cudaGridDependencySynchronize();  // g_bf ready (PDL)
#endif

#pragma unroll
    for (int t = 0; t < TPB; ++t) {
        const int w = 2 * g + t;      // tile (window-block) index within row

        // ---- Prefetch next tile while current computes ----
        if (t + 1 < TPB) {
            const float4* src = reinterpret_cast<const float4*>(xrow + 3840 * (w + 1));
            float4* dst = reinterpret_cast<float4*>(sx[(t + 1) & 1]);
#pragma unroll 4
            for (int f = tid; f < SPAN4; f += WPB)
                __pipeline_memcpy_async(&dst[f], &src[f], 16);
            __pipeline_commit();
            __pipeline_wait_prior(1); // current tile's group done; next may fly
        } else {
            __pipeline_wait_prior(0);
        }
        __syncthreads();

        // ---- In-place product: sx *= bf (bf coalesced LDG, L2-resident) ----
        float4* cur = reinterpret_cast<float4*>(sx[t & 1]);
        const float4* bf4 = reinterpret_cast<const float4*>(g_bf + 3840 * w);
#pragma unroll 4
        for (int f = tid; f < SPAN4; f += WPB) {
            float4 p = cur[f];
            float4 v = bf4[f];
            p.x *= v.x; p.y *= v.y; p.z *= v.z; p.w *= v.w;
            cur[f] = p;
        }
        __syncthreads();

        // ---- Argmax over window [15*tid, 15*tid+16): stride-15 LDS, conflict-free ----
        const float* ps = sx[t & 1] + 15 * tid;
        float best = -INFINITY;
        int bj = 0;
#pragma unroll
        for (int j = 0; j < DPC; ++j) {
            float v = ps[j];
            if (v > best) { best = v; bj = j; }
        }
        s_bj[tid] = bj;
        __syncthreads();              // last read of cur above; gates buffer reuse

        // ---- Output: coalesced chunk re-read (L2-hot) + mask + coalesced store ----
        const float4* xc4 = reinterpret_cast<const float4*>(xrow + 4096 * w);
        float4* o4 = reinterpret_cast<float4*>(out + rowoff + 4096 * w);
#pragma unroll
        for (int q = 0; q < 4; ++q) {
            int f  = tid + WPB * q;   // float4 index 0..1023
            int c  = f >> 2;          // window index within tile
            int j0 = (f & 3) << 2;    // first j covered by this float4
            int bjc = s_bj[c];
            float4 xv = xc4[f];
            float4 v;
            v.x = (bjc == j0 + 0) ? xv.x : 0.0f;
            v.y = (bjc == j0 + 1) ? xv.y : 0.0f;
            v.z = (bjc == j0 + 2) ? xv.z : 0.0f;
            v.w = (bjc == j0 + 3) ? xv.w : 0.0f;
            o4[f] = v;
        }
    }
}

extern "C" void kernel_launch(void* const* d_in, const int* in_sizes, int n_in,
                              void* d_out, int out_size) {
    const float* x  = (const float*)d_in[0];
    const float* dc = (const float*)d_in[1];
    const float* bs = (const float*)d_in[2];
    float* out = (float*)d_out;

    bf_kernel<<<NCOLS / 256, 256>>>(dc, bs);

    cudaLaunchConfig_t cfg = {};
    cfg.gridDim  = dim3(BATCH * 8, 1, 1);   // 4096 blocks, 2 tiles each
    cfg.blockDim = dim3(WPB, 1, 1);
    cfg.dynamicSmemBytes = 0;
    cfg.stream = 0;
    cudaLaunchAttribute attr[1];
    attr[0].id = cudaLaunchAttributeProgrammaticStreamSerialization;
    attr[0].val.programmaticStreamSerializationAllowed = 1;
    cfg.attrs = attr;
    cfg.numAttrs = 1;
    cudaLaunchKernelEx(&cfg, dkw_kernel, x, out);
}